// round 6
// baseline (speedup 1.0000x reference)
#include <cuda_runtime.h>
#include <cuda_fp16.h>
#include <math.h>

#define NTOK 2048
#define DIM_ 2048
#define HID_ 7168
#define NEXP 8

#define BM  128
#define BKH 32       // K halves per smem tile
#define BN1 64       // ffn1 N tile (doubled over w1/w3 -> 128 effective)
#define BN2 128      // ffn2 N tile
#define LDH 40       // half-stride (20 words): banks 20r+q all-distinct -> conflict-free frags

// ---------------- device scratch ----------------
__device__ int    g_cnt[NEXP];
__device__ int    g_tok[NEXP * NTOK];
__device__ float  g_wt [NEXP * NTOK];
__device__ __half g_act[(size_t)NTOK * 2 * HID_];   // fp16 activations (58MB)

// ---------------- helpers ----------------
__device__ __forceinline__ void mma16(float* c, const unsigned* a, const unsigned* b) {
    asm volatile(
        "mma.sync.aligned.m16n8k16.row.col.f32.f16.f16.f32 "
        "{%0,%1,%2,%3}, {%4,%5,%6,%7}, {%8,%9}, {%0,%1,%2,%3};\n"
        : "+f"(c[0]), "+f"(c[1]), "+f"(c[2]), "+f"(c[3])
        : "r"(a[0]), "r"(a[1]), "r"(a[2]), "r"(a[3]),
          "r"(b[0]), "r"(b[1]));
}

__device__ __forceinline__ unsigned pk(float lo, float hi) {
    __half2 h = __floats2half2_rn(lo, hi);
    return *reinterpret_cast<unsigned*>(&h);
}

__global__ void zero_cnt_kernel() {
    if (threadIdx.x < NEXP) g_cnt[threadIdx.x] = 0;
}

// ---------------- gating ----------------
__global__ __launch_bounds__(128) void gate_kernel(const float* __restrict__ x,
                                                   const float* __restrict__ Wg) {
    __shared__ float red[128 * NEXP];
    __shared__ float sc[NEXP];
    int t = blockIdx.x;
    const float* xr = x + (size_t)t * DIM_;
    float acc[NEXP];
#pragma unroll
    for (int e = 0; e < NEXP; e++) acc[e] = 0.f;
    for (int i = threadIdx.x; i < DIM_; i += 128) {
        float xv = xr[i];
        const float4* w4 = reinterpret_cast<const float4*>(Wg + (size_t)i * NEXP);
        float4 wa = w4[0], wb = w4[1];
        acc[0] += xv * wa.x; acc[1] += xv * wa.y;
        acc[2] += xv * wa.z; acc[3] += xv * wa.w;
        acc[4] += xv * wb.x; acc[5] += xv * wb.y;
        acc[6] += xv * wb.z; acc[7] += xv * wb.w;
    }
#pragma unroll
    for (int e = 0; e < NEXP; e++) red[threadIdx.x * NEXP + e] = acc[e];
    __syncthreads();
    if (threadIdx.x < NEXP) {
        int e = threadIdx.x;
        float s = 0.f;
        for (int i = 0; i < 128; i++) s += red[i * NEXP + e];
        sc[e] = s;
    }
    __syncthreads();
    if (threadIdx.x == 0) {
        int i1 = 0;
#pragma unroll
        for (int e = 1; e < NEXP; e++) if (sc[e] > sc[i1]) i1 = e;
        int i2 = (i1 == 0) ? 1 : 0;
#pragma unroll
        for (int e = 0; e < NEXP; e++) if (e != i1 && sc[e] > sc[i2]) i2 = e;
        float e2 = expf(sc[i2] - sc[i1]);
        float wa = 1.f / (1.f + e2);
        float wb = e2 / (1.f + e2);
        int s1 = atomicAdd(&g_cnt[i1], 1);
        g_tok[i1 * NTOK + s1] = t; g_wt[i1 * NTOK + s1] = wa;
        int s2 = atomicAdd(&g_cnt[i2], 1);
        g_tok[i2 * NTOK + s2] = t; g_wt[i2 * NTOK + s2] = wb;
    }
}

// ---------------- FFN1: gathered X @ {w1,w3} + SwiGLU -> g_act ----------------
__global__ __launch_bounds__(256, 2) void ffn1_kernel(const float* __restrict__ x,
                                                      const float* __restrict__ w1,
                                                      const float* __restrict__ w3) {
    __shared__ __half As[2][BM][LDH];
    __shared__ __half B1s[2][BN1][LDH];
    __shared__ __half B3s[2][BN1][LDH];
    __shared__ int toks[BM];

    int e = blockIdx.z;
    int cnt = g_cnt[e];
    int m0 = blockIdx.x * BM;
    if (m0 >= cnt) return;
    int n0 = blockIdx.y * BN1;
    int base = 0;
#pragma unroll
    for (int i = 0; i < NEXP; i++) base += (i < e) ? g_cnt[i] : 0;
    const float* W1 = w1 + (size_t)e * DIM_ * HID_;
    const float* W3 = w3 + (size_t)e * DIM_ * HID_;

    int tid = threadIdx.x;
    if (tid < BM) {
        int m = m0 + tid;
        toks[tid] = (m < cnt) ? g_tok[e * NTOK + m] : -1;
    }
    __syncthreads();

    int lane = tid & 31, warp = tid >> 5;
    // A loader: rows lar, lar+64; floats (tid&3)*8 .. +7 (k axis)
    int lar = tid >> 2, lac = (tid & 3) << 3;
    int lt0 = toks[lar], lt1 = toks[lar + 64];
    const float* xr0 = x + (size_t)(lt0 < 0 ? 0 : lt0) * DIM_;
    const float* xr1 = x + (size_t)(lt1 < 0 ? 0 : lt1) * DIM_;
    // B loader (transpose): kp = tid&15 (k pair 2kp), ng = tid>>4 (4 n-rows)
    int kp = tid & 15, ng = tid >> 4;

    int wm = (warp >> 1) << 5;    // 0,32,64,96
    int wn = (warp & 1) << 5;     // 0,32
    int r = lane >> 2, q = lane & 3;

    float c1[2][4][4], c3[2][4][4];
#pragma unroll
    for (int i = 0; i < 2; i++)
#pragma unroll
        for (int j = 0; j < 4; j++)
#pragma unroll
            for (int k = 0; k < 4; k++) { c1[i][j][k] = 0.f; c3[i][j][k] = 0.f; }

#define F1_STAGE(K0, BUF) do {                                                         \
    float4 z4 = make_float4(0.f, 0.f, 0.f, 0.f);                                       \
    float4 a00 = z4, a01 = z4, a10 = z4, a11 = z4;                                     \
    if (lt0 >= 0) { a00 = *reinterpret_cast<const float4*>(xr0 + (K0) + lac);          \
                    a01 = *reinterpret_cast<const float4*>(xr0 + (K0) + lac + 4); }    \
    if (lt1 >= 0) { a10 = *reinterpret_cast<const float4*>(xr1 + (K0) + lac);          \
                    a11 = *reinterpret_cast<const float4*>(xr1 + (K0) + lac + 4); }    \
    const float* b1p0 = W1 + (size_t)((K0) + 2 * kp) * HID_ + n0 + (ng << 2);          \
    const float* b3p0 = W3 + (size_t)((K0) + 2 * kp) * HID_ + n0 + (ng << 2);          \
    float4 w1a = *reinterpret_cast<const float4*>(b1p0);                               \
    float4 w1b = *reinterpret_cast<const float4*>(b1p0 + HID_);                        \
    float4 w3a = *reinterpret_cast<const float4*>(b3p0);                               \
    float4 w3b = *reinterpret_cast<const float4*>(b3p0 + HID_);                        \
    unsigned* ap0 = reinterpret_cast<unsigned*>(&As[BUF][lar][lac]);                   \
    ap0[0] = pk(a00.x, a00.y); ap0[1] = pk(a00.z, a00.w);                              \
    ap0[2] = pk(a01.x, a01.y); ap0[3] = pk(a01.z, a01.w);                              \
    unsigned* ap1 = reinterpret_cast<unsigned*>(&As[BUF][lar + 64][lac]);              \
    ap1[0] = pk(a10.x, a10.y); ap1[1] = pk(a10.z, a10.w);                              \
    ap1[2] = pk(a11.x, a11.y); ap1[3] = pk(a11.z, a11.w);                              \
    int nr = ng << 2;                                                                  \
    *reinterpret_cast<unsigned*>(&B1s[BUF][nr + 0][2 * kp]) = pk(w1a.x, w1b.x);        \
    *reinterpret_cast<unsigned*>(&B1s[BUF][nr + 1][2 * kp]) = pk(w1a.y, w1b.y);        \
    *reinterpret_cast<unsigned*>(&B1s[BUF][nr + 2][2 * kp]) = pk(w1a.z, w1b.z);        \
    *reinterpret_cast<unsigned*>(&B1s[BUF][nr + 3][2 * kp]) = pk(w1a.w, w1b.w);        \
    *reinterpret_cast<unsigned*>(&B3s[BUF][nr + 0][2 * kp]) = pk(w3a.x, w3b.x);        \
    *reinterpret_cast<unsigned*>(&B3s[BUF][nr + 1][2 * kp]) = pk(w3a.y, w3b.y);        \
    *reinterpret_cast<unsigned*>(&B3s[BUF][nr + 2][2 * kp]) = pk(w3a.z, w3b.z);        \
    *reinterpret_cast<unsigned*>(&B3s[BUF][nr + 3][2 * kp]) = pk(w3a.w, w3b.w);        \
} while (0)

    F1_STAGE(0, 0);
    __syncthreads();

    const int NT = DIM_ / BKH;
    for (int t = 0; t < NT; t++) {
        int cur = t & 1;
        if (t + 1 < NT) F1_STAGE((t + 1) * BKH, cur ^ 1);
#pragma unroll
        for (int kk = 0; kk < 2; kk++) {
            int ko = kk << 4;
            unsigned a[2][4];
#pragma unroll
            for (int mi = 0; mi < 2; mi++) {
                int rb = wm + (mi << 4) + r;
                a[mi][0] = *reinterpret_cast<unsigned*>(&As[cur][rb][ko + 2 * q]);
                a[mi][1] = *reinterpret_cast<unsigned*>(&As[cur][rb + 8][ko + 2 * q]);
                a[mi][2] = *reinterpret_cast<unsigned*>(&As[cur][rb][ko + 2 * q + 8]);
                a[mi][3] = *reinterpret_cast<unsigned*>(&As[cur][rb + 8][ko + 2 * q + 8]);
            }
#pragma unroll
            for (int ni = 0; ni < 4; ni++) {
                int nb = wn + (ni << 3) + r;
                unsigned b1f[2], b3f[2];
                b1f[0] = *reinterpret_cast<unsigned*>(&B1s[cur][nb][ko + 2 * q]);
                b1f[1] = *reinterpret_cast<unsigned*>(&B1s[cur][nb][ko + 2 * q + 8]);
                b3f[0] = *reinterpret_cast<unsigned*>(&B3s[cur][nb][ko + 2 * q]);
                b3f[1] = *reinterpret_cast<unsigned*>(&B3s[cur][nb][ko + 2 * q + 8]);
#pragma unroll
                for (int mi = 0; mi < 2; mi++) {
                    mma16(c1[mi][ni], a[mi], b1f);
                    mma16(c3[mi][ni], a[mi], b3f);
                }
            }
        }
        __syncthreads();
    }

    // epilogue: SwiGLU -> g_act (half2 stores)
#pragma unroll
    for (int mi = 0; mi < 2; mi++) {
#pragma unroll
        for (int rr = 0; rr < 2; rr++) {
            int m = m0 + wm + (mi << 4) + r + (rr << 3);
            if (m < cnt) {
                size_t rowoff = (size_t)(base + m) * HID_;
#pragma unroll
                for (int ni = 0; ni < 4; ni++) {
                    int col = n0 + wn + (ni << 3) + (q << 1);
                    float u0 = c1[mi][ni][(rr << 1)],     v0 = c3[mi][ni][(rr << 1)];
                    float u1 = c1[mi][ni][(rr << 1) + 1], v1 = c3[mi][ni][(rr << 1) + 1];
                    float h0 = (u0 / (1.f + expf(-u0))) * v0;
                    float h1 = (u1 / (1.f + expf(-u1))) * v1;
                    *reinterpret_cast<unsigned*>(&g_act[rowoff + col]) = pk(h0, h1);
                }
            }
        }
    }
}

// ---------------- FFN2: g_act @ w2 -> weighted scatter-add ----------------
__global__ __launch_bounds__(256, 2) void ffn2_kernel(const float* __restrict__ w2,
                                                      float* __restrict__ out) {
    __shared__ __half As[2][BM][LDH];
    __shared__ __half Bs[2][BN2][LDH];

    int e = blockIdx.z;
    int cnt = g_cnt[e];
    int m0 = blockIdx.x * BM;
    if (m0 >= cnt) return;
    int n0 = blockIdx.y * BN2;
    int base = 0;
#pragma unroll
    for (int i = 0; i < NEXP; i++) base += (i < e) ? g_cnt[i] : 0;
    const float* W2 = w2 + (size_t)e * HID_ * DIM_;

    int tid = threadIdx.x;
    int lane = tid & 31, warp = tid >> 5;
    // A loader: rows lar, lar+64; halves (tid&3)*8 (16B-aligned uint4 loads)
    int lar = tid >> 2, lac = (tid & 3) << 3;
    bool v0 = (m0 + lar) < cnt, v1 = (m0 + lar + 64) < cnt;
    const __half* ar0 = g_act + (size_t)(base + m0 + (v0 ? lar : 0)) * HID_;
    const __half* ar1 = g_act + (size_t)(base + m0 + (v1 ? lar + 64 : 0)) * HID_;
    // B loader: kp = tid&15, ng = tid>>4; two n-blocks (4ng, 4ng+64)
    int kp = tid & 15, ng = tid >> 4;

    int wm = (warp >> 1) << 5;   // 0,32,64,96
    int wn = (warp & 1) << 6;    // 0,64
    int r = lane >> 2, q = lane & 3;

    float c[2][8][4];
#pragma unroll
    for (int i = 0; i < 2; i++)
#pragma unroll
        for (int j = 0; j < 8; j++)
#pragma unroll
            for (int k = 0; k < 4; k++) c[i][j][k] = 0.f;

#define F2_STAGE(K0, BUF) do {                                                         \
    uint4 a0 = make_uint4(0, 0, 0, 0), a1 = make_uint4(0, 0, 0, 0);                    \
    if (v0) a0 = *reinterpret_cast<const uint4*>(ar0 + (K0) + lac);                    \
    if (v1) a1 = *reinterpret_cast<const uint4*>(ar1 + (K0) + lac);                    \
    const float* bp0 = W2 + (size_t)((K0) + 2 * kp) * DIM_ + n0 + (ng << 2);           \
    float4 wa0 = *reinterpret_cast<const float4*>(bp0);                                \
    float4 wb0 = *reinterpret_cast<const float4*>(bp0 + DIM_);                         \
    float4 wa1 = *reinterpret_cast<const float4*>(bp0 + 64);                           \
    float4 wb1 = *reinterpret_cast<const float4*>(bp0 + DIM_ + 64);                    \
    unsigned* ap0 = reinterpret_cast<unsigned*>(&As[BUF][lar][lac]);                   \
    ap0[0] = a0.x; ap0[1] = a0.y; ap0[2] = a0.z; ap0[3] = a0.w;                        \
    unsigned* ap1 = reinterpret_cast<unsigned*>(&As[BUF][lar + 64][lac]);              \
    ap1[0] = a1.x; ap1[1] = a1.y; ap1[2] = a1.z; ap1[3] = a1.w;                        \
    int nr = ng << 2;                                                                  \
    *reinterpret_cast<unsigned*>(&Bs[BUF][nr + 0][2 * kp]) = pk(wa0.x, wb0.x);         \
    *reinterpret_cast<unsigned*>(&Bs[BUF][nr + 1][2 * kp]) = pk(wa0.y, wb0.y);         \
    *reinterpret_cast<unsigned*>(&Bs[BUF][nr + 2][2 * kp]) = pk(wa0.z, wb0.z);         \
    *reinterpret_cast<unsigned*>(&Bs[BUF][nr + 3][2 * kp]) = pk(wa0.w, wb0.w);         \
    *reinterpret_cast<unsigned*>(&Bs[BUF][nr + 64][2 * kp]) = pk(wa1.x, wb1.x);        \
    *reinterpret_cast<unsigned*>(&Bs[BUF][nr + 65][2 * kp]) = pk(wa1.y, wb1.y);        \
    *reinterpret_cast<unsigned*>(&Bs[BUF][nr + 66][2 * kp]) = pk(wa1.z, wb1.z);        \
    *reinterpret_cast<unsigned*>(&Bs[BUF][nr + 67][2 * kp]) = pk(wa1.w, wb1.w);        \
} while (0)

    F2_STAGE(0, 0);
    __syncthreads();

    const int NT = HID_ / BKH;
    for (int t = 0; t < NT; t++) {
        int cur = t & 1;
        if (t + 1 < NT) F2_STAGE((t + 1) * BKH, cur ^ 1);
#pragma unroll
        for (int kk = 0; kk < 2; kk++) {
            int ko = kk << 4;
            unsigned a[2][4];
#pragma unroll
            for (int mi = 0; mi < 2; mi++) {
                int rb = wm + (mi << 4) + r;
                a[mi][0] = *reinterpret_cast<unsigned*>(&As[cur][rb][ko + 2 * q]);
                a[mi][1] = *reinterpret_cast<unsigned*>(&As[cur][rb + 8][ko + 2 * q]);
                a[mi][2] = *reinterpret_cast<unsigned*>(&As[cur][rb][ko + 2 * q + 8]);
                a[mi][3] = *reinterpret_cast<unsigned*>(&As[cur][rb + 8][ko + 2 * q + 8]);
            }
            unsigned b[8][2];
#pragma unroll
            for (int ni = 0; ni < 8; ni++) {
                int nb = wn + (ni << 3) + r;
                b[ni][0] = *reinterpret_cast<unsigned*>(&Bs[cur][nb][ko + 2 * q]);
                b[ni][1] = *reinterpret_cast<unsigned*>(&Bs[cur][nb][ko + 2 * q + 8]);
            }
#pragma unroll
            for (int ni = 0; ni < 8; ni++)
#pragma unroll
                for (int mi = 0; mi < 2; mi++)
                    mma16(c[mi][ni], a[mi], b[ni]);
        }
        __syncthreads();
    }

    // epilogue: weighted scatter-add
#pragma unroll
    for (int mi = 0; mi < 2; mi++) {
#pragma unroll
        for (int rr = 0; rr < 2; rr++) {
            int m = m0 + wm + (mi << 4) + r + (rr << 3);
            if (m < cnt) {
                int t = g_tok[e * NTOK + m];
                float wgt = g_wt[e * NTOK + m];
                float* orow = out + (size_t)t * DIM_;
#pragma unroll
                for (int ni = 0; ni < 8; ni++) {
                    int col = n0 + wn + (ni << 3) + (q << 1);
                    atomicAdd(&orow[col],     wgt * c[mi][ni][(rr << 1)]);
                    atomicAdd(&orow[col + 1], wgt * c[mi][ni][(rr << 1) + 1]);
                }
            }
        }
    }
}

// ---------------- launch ----------------
extern "C" void kernel_launch(void* const* d_in, const int* in_sizes, int n_in,
                              void* d_out, int out_size) {
    const float* x  = (const float*)d_in[0];
    const float* Wg = (const float*)d_in[1];
    const float* w1 = (const float*)d_in[2];
    const float* w3 = (const float*)d_in[3];
    const float* w2 = (const float*)d_in[4];
    float* out = (float*)d_out;
    (void)in_sizes; (void)n_in;

    cudaMemsetAsync(out, 0, (size_t)out_size * sizeof(float), 0);
    zero_cnt_kernel<<<1, 32>>>();
    gate_kernel<<<NTOK, 128>>>(x, Wg);
    ffn1_kernel<<<dim3(NTOK / BM, HID_ / BN1, NEXP), 256>>>(x, w1, w3);
    ffn2_kernel<<<dim3(NTOK / BM, DIM_ / BN2, NEXP), 256>>>(w2, out);
}

// round 8
// speedup vs baseline: 1.6113x; 1.6113x over previous
#include <cuda_runtime.h>
#include <cuda_fp16.h>
#include <math.h>
#include <cstdint>

#define NTOK 2048
#define DIM_ 2048
#define HID_ 7168
#define NEXP 8
#define BKH  64                 // k halves per smem tile (128B rows)
#define NT1  (DIM_/BKH)         // 32
#define NT2  (HID_/BKH)         // 112

// ---------------- device scratch ----------------
__device__ int    g_cnt[NEXP];
__device__ int    g_tok[NEXP * NTOK];
__device__ float  g_wt [NEXP * NTOK];
__device__ __half g_act[(size_t)NTOK * 2 * HID_];
__device__ __half g_x16[(size_t)NTOK * DIM_];

// ---------------- helpers ----------------
__device__ __forceinline__ unsigned pk(float lo, float hi) {
    __half2 h = __floats2half2_rn(lo, hi);
    return *reinterpret_cast<unsigned*>(&h);
}
__device__ __forceinline__ void mma16(float* c, const unsigned* a, const unsigned* b) {
    asm volatile(
        "mma.sync.aligned.m16n8k16.row.col.f32.f16.f16.f32 "
        "{%0,%1,%2,%3}, {%4,%5,%6,%7}, {%8,%9}, {%0,%1,%2,%3};\n"
        : "+f"(c[0]), "+f"(c[1]), "+f"(c[2]), "+f"(c[3])
        : "r"(a[0]), "r"(a[1]), "r"(a[2]), "r"(a[3]), "r"(b[0]), "r"(b[1]));
}

#define LDSM(d0,d1,d2,d3,ad) asm volatile( \
    "ldmatrix.sync.aligned.m8n8.x4.shared.b16 {%0,%1,%2,%3}, [%4];" \
    : "=r"(d0),"=r"(d1),"=r"(d2),"=r"(d3) : "r"(ad))
#define LDSMT(d0,d1,d2,d3,ad) asm volatile( \
    "ldmatrix.sync.aligned.m8n8.x4.trans.shared.b16 {%0,%1,%2,%3}, [%4];" \
    : "=r"(d0),"=r"(d1),"=r"(d2),"=r"(d3) : "r"(ad))
#define CPA16(dst,src) asm volatile( \
    "cp.async.cg.shared.global [%0], [%1], 16;" :: "r"(dst), "l"(src) : "memory")
#define CPCOMMIT() asm volatile("cp.async.commit_group;" ::: "memory")
#define CPWAIT()   asm volatile("cp.async.wait_group 0;" ::: "memory")
#define STS4(ad,a,b,c,d) asm volatile( \
    "st.shared.v4.b32 [%0], {%1,%2,%3,%4};" :: "r"(ad),"r"(a),"r"(b),"r"(c),"r"(d) : "memory")

// A tile frag addr: rows of 128B, swizzle chunk ^= (m&7)
__device__ __forceinline__ uint32_t a_addr(uint32_t aB, int mbase, int ko, int lane) {
    int m  = mbase + (lane & 7) + ((lane >> 3) & 1) * 8;
    int cb = 2 * ko + ((lane >> 4) << 4);
    return aB + m * 128 + (cb ^ ((m & 7) << 4));
}
// B tile frag addr (trans): row k (stride bytes), swizzle chunk ^= (k&7)
__device__ __forceinline__ uint32_t b_addr(uint32_t bB, int nbase, int ko, int lane, int stride) {
    int k  = ko + ((lane >> 3) & 1) * 8 + (lane & 7);
    int nb = nbase + ((lane >> 4) << 3);
    return bB + k * stride + ((2 * nb) ^ ((k & 7) << 4));
}

// ---------------- misc kernels ----------------
__global__ void cvt_x_kernel(const float* __restrict__ x) {
    size_t i = ((size_t)blockIdx.x * blockDim.x + threadIdx.x) * 4;
    float4 v = *reinterpret_cast<const float4*>(x + i);
    uint2 u;
    u.x = pk(v.x, v.y); u.y = pk(v.z, v.w);
    *reinterpret_cast<uint2*>(&g_x16[i]) = u;
}

__global__ void zero_cnt_kernel() {
    if (threadIdx.x < NEXP) g_cnt[threadIdx.x] = 0;
}

__global__ __launch_bounds__(128) void gate_kernel(const float* __restrict__ x,
                                                   const float* __restrict__ Wg) {
    __shared__ float red[128 * NEXP];
    __shared__ float sc[NEXP];
    int t = blockIdx.x;
    const float* xr = x + (size_t)t * DIM_;
    float acc[NEXP];
#pragma unroll
    for (int e = 0; e < NEXP; e++) acc[e] = 0.f;
    for (int i = threadIdx.x; i < DIM_; i += 128) {
        float xv = xr[i];
        const float4* w4 = reinterpret_cast<const float4*>(Wg + (size_t)i * NEXP);
        float4 wa = w4[0], wb = w4[1];
        acc[0] += xv * wa.x; acc[1] += xv * wa.y;
        acc[2] += xv * wa.z; acc[3] += xv * wa.w;
        acc[4] += xv * wb.x; acc[5] += xv * wb.y;
        acc[6] += xv * wb.z; acc[7] += xv * wb.w;
    }
#pragma unroll
    for (int e = 0; e < NEXP; e++) red[threadIdx.x * NEXP + e] = acc[e];
    __syncthreads();
    if (threadIdx.x < NEXP) {
        int e = threadIdx.x;
        float s = 0.f;
        for (int i = 0; i < 128; i++) s += red[i * NEXP + e];
        sc[e] = s;
    }
    __syncthreads();
    if (threadIdx.x == 0) {
        int i1 = 0;
#pragma unroll
        for (int e = 1; e < NEXP; e++) if (sc[e] > sc[i1]) i1 = e;
        int i2 = (i1 == 0) ? 1 : 0;
#pragma unroll
        for (int e = 0; e < NEXP; e++) if (e != i1 && sc[e] > sc[i2]) i2 = e;
        float e2 = expf(sc[i2] - sc[i1]);
        float wa = 1.f / (1.f + e2);
        float wb = e2 / (1.f + e2);
        int s1 = atomicAdd(&g_cnt[i1], 1);
        g_tok[i1 * NTOK + s1] = t; g_wt[i1 * NTOK + s1] = wa;
        int s2 = atomicAdd(&g_cnt[i2], 1);
        g_tok[i2 * NTOK + s2] = t; g_wt[i2 * NTOK + s2] = wb;
    }
}

// ---------------- FFN1: X16 @ {w1,w3} + SwiGLU -> g_act ----------------
// BM=64, per-matrix BN=64, BKH=64. smem: A 2x8KB, B1 2x8KB, B3 2x8KB = 48KB dynamic.
__global__ __launch_bounds__(256, 2) void ffn1_kernel(const float* __restrict__ w1,
                                                      const float* __restrict__ w3) {
    extern __shared__ __align__(128) char smem[];
    __shared__ int toks[64];
    uint32_t sA  = (uint32_t)__cvta_generic_to_shared(smem);
    uint32_t sB1 = sA + 16384;
    uint32_t sB3 = sA + 32768;

    int e = blockIdx.z, cnt = g_cnt[e];
    int m0 = blockIdx.x * 64;
    if (m0 >= cnt) return;
    int n0 = blockIdx.y * 64;
    int base = 0;
#pragma unroll
    for (int i = 0; i < NEXP; i++) base += (i < e) ? g_cnt[i] : 0;
    const float* W1 = w1 + (size_t)e * DIM_ * HID_;
    const float* W3 = w3 + (size_t)e * DIM_ * HID_;

    int tid = threadIdx.x, lane = tid & 31, w = tid >> 5;
    if (tid < 64) {
        int m = m0 + tid;
        toks[tid] = (m < cnt) ? g_tok[e * NTOK + m] : 0;
    }
    __syncthreads();

    // loaders
    int am = tid >> 2, t3 = tid & 3;           // A: row am, chunks {t3, t3+4}
    const __half* asrc = g_x16 + (size_t)toks[am] * DIM_;
    int kr = am;                                // B: k-row kr, chunks {t3, t3+4}

    // warp tile: 2m x 2n(8) per matrix
    int wm = (w >> 2) * 32, wn1 = (w & 3) * 16;
    int r = lane >> 2, q = lane & 3;

    float c1[2][2][4], c3[2][2][4];
#pragma unroll
    for (int i = 0; i < 2; i++)
#pragma unroll
        for (int j = 0; j < 2; j++)
#pragma unroll
            for (int k = 0; k < 4; k++) { c1[i][j][k] = 0.f; c3[i][j][k] = 0.f; }

    float4 br1[4], br3[4];

#define F1_CPA(K0, BUF) do {                                                   \
    uint32_t b_ = sA + (BUF) * 8192 + am * 128;                                \
    CPA16(b_ + ((t3 * 16)       ^ ((am & 7) << 4)), asrc + (K0) + t3 * 8);     \
    CPA16(b_ + (((t3+4) * 16)   ^ ((am & 7) << 4)), asrc + (K0) + (t3+4) * 8); \
    CPCOMMIT();                                                                \
} while (0)

#define F1_LDGB(K0) do {                                                       \
    const float* p1 = W1 + (size_t)((K0) + kr) * HID_ + n0;                    \
    const float* p3 = W3 + (size_t)((K0) + kr) * HID_ + n0;                    \
    br1[0] = *reinterpret_cast<const float4*>(p1 + t3 * 8);                    \
    br1[1] = *reinterpret_cast<const float4*>(p1 + t3 * 8 + 4);                \
    br1[2] = *reinterpret_cast<const float4*>(p1 + (t3+4) * 8);                \
    br1[3] = *reinterpret_cast<const float4*>(p1 + (t3+4) * 8 + 4);            \
    br3[0] = *reinterpret_cast<const float4*>(p3 + t3 * 8);                    \
    br3[1] = *reinterpret_cast<const float4*>(p3 + t3 * 8 + 4);                \
    br3[2] = *reinterpret_cast<const float4*>(p3 + (t3+4) * 8);                \
    br3[3] = *reinterpret_cast<const float4*>(p3 + (t3+4) * 8 + 4);            \
} while (0)

#define F1_STSB(BUF) do {                                                      \
    uint32_t b1_ = sB1 + (BUF) * 8192 + kr * 128;                              \
    uint32_t b3_ = sB3 + (BUF) * 8192 + kr * 128;                              \
    uint32_t sw0 = (t3 * 16) ^ ((kr & 7) << 4);                                \
    uint32_t sw1 = ((t3+4) * 16) ^ ((kr & 7) << 4);                            \
    STS4(b1_ + sw0, pk(br1[0].x,br1[0].y), pk(br1[0].z,br1[0].w),              \
                    pk(br1[1].x,br1[1].y), pk(br1[1].z,br1[1].w));             \
    STS4(b1_ + sw1, pk(br1[2].x,br1[2].y), pk(br1[2].z,br1[2].w),              \
                    pk(br1[3].x,br1[3].y), pk(br1[3].z,br1[3].w));             \
    STS4(b3_ + sw0, pk(br3[0].x,br3[0].y), pk(br3[0].z,br3[0].w),              \
                    pk(br3[1].x,br3[1].y), pk(br3[1].z,br3[1].w));             \
    STS4(b3_ + sw1, pk(br3[2].x,br3[2].y), pk(br3[2].z,br3[2].w),              \
                    pk(br3[3].x,br3[3].y), pk(br3[3].z,br3[3].w));             \
} while (0)

    // prologue
    F1_CPA(0, 0);
    F1_LDGB(0);
    F1_STSB(0);
    CPWAIT();
    __syncthreads();

    for (int t = 0; t < NT1; t++) {
        int cur = t & 1;
        if (t + 1 < NT1) { F1_CPA((t + 1) * BKH, cur ^ 1); F1_LDGB((t + 1) * BKH); }
        uint32_t aB = sA + cur * 8192, b1B = sB1 + cur * 8192, b3B = sB3 + cur * 8192;
#pragma unroll
        for (int kk = 0; kk < 4; kk++) {
            int ko = kk << 4;
            unsigned a0[4], a1[4], f1[2][2], f3[2][2];
            LDSM(a0[0], a0[1], a0[2], a0[3], a_addr(aB, wm, ko, lane));
            LDSM(a1[0], a1[1], a1[2], a1[3], a_addr(aB, wm + 16, ko, lane));
            LDSMT(f1[0][0], f1[0][1], f1[1][0], f1[1][1], b_addr(b1B, wn1, ko, lane, 128));
            LDSMT(f3[0][0], f3[0][1], f3[1][0], f3[1][1], b_addr(b3B, wn1, ko, lane, 128));
#pragma unroll
            for (int ni = 0; ni < 2; ni++) {
                mma16(c1[0][ni], a0, f1[ni]); mma16(c1[1][ni], a1, f1[ni]);
                mma16(c3[0][ni], a0, f3[ni]); mma16(c3[1][ni], a1, f3[ni]);
            }
        }
        if (t + 1 < NT1) F1_STSB(cur ^ 1);
        CPWAIT();
        __syncthreads();
    }

    // epilogue: SwiGLU -> g_act (half2)
#pragma unroll
    for (int mi = 0; mi < 2; mi++) {
#pragma unroll
        for (int rr = 0; rr < 2; rr++) {
            int m = m0 + wm + (mi << 4) + r + (rr << 3);
            if (m < cnt) {
                size_t rowoff = (size_t)(base + m) * HID_;
#pragma unroll
                for (int ni = 0; ni < 2; ni++) {
                    int col = n0 + wn1 + (ni << 3) + (q << 1);
                    float u0 = c1[mi][ni][(rr << 1)],     v0 = c3[mi][ni][(rr << 1)];
                    float u1 = c1[mi][ni][(rr << 1) + 1], v1 = c3[mi][ni][(rr << 1) + 1];
                    float h0 = (u0 / (1.f + expf(-u0))) * v0;
                    float h1 = (u1 / (1.f + expf(-u1))) * v1;
                    *reinterpret_cast<unsigned*>(&g_act[rowoff + col]) = pk(h0, h1);
                }
            }
        }
    }
}

// ---------------- FFN2: g_act @ w2 -> weighted scatter ----------------
// BM=64, BN=128, BKH=64. smem: A 2x8KB + B 2x16KB = 48KB dynamic.
__global__ __launch_bounds__(256, 2) void ffn2_kernel(const float* __restrict__ w2,
                                                      float* __restrict__ out) {
    extern __shared__ __align__(128) char smem[];
    uint32_t sA = (uint32_t)__cvta_generic_to_shared(smem);
    uint32_t sB = sA + 16384;

    int e = blockIdx.z, cnt = g_cnt[e];
    int m0 = blockIdx.x * 64;
    if (m0 >= cnt) return;
    int n0 = blockIdx.y * 128;
    int base = 0;
#pragma unroll
    for (int i = 0; i < NEXP; i++) base += (i < e) ? g_cnt[i] : 0;
    const float* W2 = w2 + (size_t)e * HID_ * DIM_;

    int tid = threadIdx.x, lane = tid & 31, w = tid >> 5;
    int am = tid >> 2, t3 = tid & 3;
    int arow = base + min(m0 + am, cnt - 1);
    const __half* asrc = g_act + (size_t)arow * HID_;
    int kr = am;

    int wm = (w >> 2) * 32, wn = (w & 3) * 32;
    int r = lane >> 2, q = lane & 3;

    float c[2][4][4];
#pragma unroll
    for (int i = 0; i < 2; i++)
#pragma unroll
        for (int j = 0; j < 4; j++)
#pragma unroll
            for (int k = 0; k < 4; k++) c[i][j][k] = 0.f;

    float4 br[8];

#define F2_CPA(K0, BUF) do {                                                   \
    uint32_t b_ = sA + (BUF) * 8192 + am * 128;                                \
    CPA16(b_ + ((t3 * 16)     ^ ((am & 7) << 4)), asrc + (K0) + t3 * 8);       \
    CPA16(b_ + (((t3+4) * 16) ^ ((am & 7) << 4)), asrc + (K0) + (t3+4) * 8);   \
    CPCOMMIT();                                                                \
} while (0)

#define F2_LDGB(K0) do {                                                       \
    const float* p = W2 + (size_t)((K0) + kr) * DIM_ + n0;                     \
    _Pragma("unroll")                                                          \
    for (int j = 0; j < 4; j++) {                                              \
        int cc = t3 + 4 * j;                                                   \
        br[2*j]   = *reinterpret_cast<const float4*>(p + cc * 8);              \
        br[2*j+1] = *reinterpret_cast<const float4*>(p + cc * 8 + 4);          \
    }                                                                          \
} while (0)

#define F2_STSB(BUF) do {                                                      \
    uint32_t b_ = sB + (BUF) * 16384 + kr * 256;                               \
    _Pragma("unroll")                                                          \
    for (int j = 0; j < 4; j++) {                                              \
        int cc = t3 + 4 * j;                                                   \
        uint32_t ad = b_ + ((cc * 16) ^ ((kr & 7) << 4));                      \
        STS4(ad, pk(br[2*j].x, br[2*j].y),   pk(br[2*j].z, br[2*j].w),         \
                 pk(br[2*j+1].x, br[2*j+1].y), pk(br[2*j+1].z, br[2*j+1].w));  \
    }                                                                          \
} while (0)

    F2_CPA(0, 0);
    F2_LDGB(0);
    F2_STSB(0);
    CPWAIT();
    __syncthreads();

    for (int t = 0; t < NT2; t++) {
        int cur = t & 1;
        if (t + 1 < NT2) { F2_CPA((t + 1) * BKH, cur ^ 1); F2_LDGB((t + 1) * BKH); }
        uint32_t aB = sA + cur * 8192, bB = sB + cur * 16384;
#pragma unroll
        for (int kk = 0; kk < 4; kk++) {
            int ko = kk << 4;
            unsigned a0[4], a1[4], bf[4][2];
            LDSM(a0[0], a0[1], a0[2], a0[3], a_addr(aB, wm, ko, lane));
            LDSM(a1[0], a1[1], a1[2], a1[3], a_addr(aB, wm + 16, ko, lane));
            LDSMT(bf[0][0], bf[0][1], bf[1][0], bf[1][1], b_addr(bB, wn, ko, lane, 256));
            LDSMT(bf[2][0], bf[2][1], bf[3][0], bf[3][1], b_addr(bB, wn + 16, ko, lane, 256));
#pragma unroll
            for (int ni = 0; ni < 4; ni++) {
                mma16(c[0][ni], a0, bf[ni]);
                mma16(c[1][ni], a1, bf[ni]);
            }
        }
        if (t + 1 < NT2) F2_STSB(cur ^ 1);
        CPWAIT();
        __syncthreads();
    }

    // epilogue: weighted scatter-add
#pragma unroll
    for (int mi = 0; mi < 2; mi++) {
#pragma unroll
        for (int rr = 0; rr < 2; rr++) {
            int m = m0 + wm + (mi << 4) + r + (rr << 3);
            if (m < cnt) {
                int tk = g_tok[e * NTOK + m];
                float wgt = g_wt[e * NTOK + m];
                float* orow = out + (size_t)tk * DIM_;
#pragma unroll
                for (int ni = 0; ni < 4; ni++) {
                    int col = n0 + wn + (ni << 3) + (q << 1);
                    atomicAdd(&orow[col],     wgt * c[mi][ni][(rr << 1)]);
                    atomicAdd(&orow[col + 1], wgt * c[mi][ni][(rr << 1) + 1]);
                }
            }
        }
    }
}

// ---------------- launch ----------------
extern "C" void kernel_launch(void* const* d_in, const int* in_sizes, int n_in,
                              void* d_out, int out_size) {
    const float* x  = (const float*)d_in[0];
    const float* Wg = (const float*)d_in[1];
    const float* w1 = (const float*)d_in[2];
    const float* w3 = (const float*)d_in[3];
    const float* w2 = (const float*)d_in[4];
    float* out = (float*)d_out;
    (void)in_sizes; (void)n_in;

    static int attr_done = 0;
    if (!attr_done) {
        cudaFuncSetAttribute(ffn1_kernel, cudaFuncAttributeMaxDynamicSharedMemorySize, 49152);
        cudaFuncSetAttribute(ffn2_kernel, cudaFuncAttributeMaxDynamicSharedMemorySize, 49152);
        attr_done = 1;
    }

    cudaMemsetAsync(out, 0, (size_t)out_size * sizeof(float), 0);
    cvt_x_kernel<<<(NTOK * DIM_) / (256 * 4), 256>>>(x);
    zero_cnt_kernel<<<1, 32>>>();
    gate_kernel<<<NTOK, 128>>>(x, Wg);
    ffn1_kernel<<<dim3(NTOK / 64, HID_ / 64, NEXP), 256, 49152>>>(w1, w3);
    ffn2_kernel<<<dim3(NTOK / 64, DIM_ / 128, NEXP), 256, 49152>>>(w2, out);
}

// round 11
// speedup vs baseline: 1.9249x; 1.1946x over previous
#include <cuda_runtime.h>
#include <cuda_fp16.h>
#include <math.h>
#include <cstdint>

#define NTOK 2048
#define DIM_ 2048
#define HID_ 7168
#define NEXP 8
#define BKH  64                 // k halves per smem tile
#define NT1  (DIM_/BKH)         // 32
#define NT2  (HID_/BKH)         // 112

#define WSZ  ((size_t)DIM_ * HID_)          // halves per expert weight matrix
#define W3OFF ((size_t)NEXP * WSZ)
#define W2OFF ((size_t)2 * NEXP * WSZ)

// ---------------- device scratch ----------------
__device__ int    g_cnt[NEXP];
__device__ int    g_tok[NEXP * NTOK];
__device__ float  g_wt [NEXP * NTOK];
__device__ __half g_act[(size_t)NTOK * 2 * HID_];
__device__ __half g_x16[(size_t)NTOK * DIM_];
__device__ __half g_w16[(size_t)3 * NEXP * WSZ];    // fp16 w1|w3|w2 (704MB)

// ---------------- helpers ----------------
__device__ __forceinline__ unsigned pk(float lo, float hi) {
    __half2 h = __floats2half2_rn(lo, hi);
    return *reinterpret_cast<unsigned*>(&h);
}
__device__ __forceinline__ void mma16(float* c, const unsigned* a, const unsigned* b) {
    asm volatile(
        "mma.sync.aligned.m16n8k16.row.col.f32.f16.f16.f32 "
        "{%0,%1,%2,%3}, {%4,%5,%6,%7}, {%8,%9}, {%0,%1,%2,%3};\n"
        : "+f"(c[0]), "+f"(c[1]), "+f"(c[2]), "+f"(c[3])
        : "r"(a[0]), "r"(a[1]), "r"(a[2]), "r"(a[3]), "r"(b[0]), "r"(b[1]));
}

#define LDSM(d0,d1,d2,d3,ad) asm volatile( \
    "ldmatrix.sync.aligned.m8n8.x4.shared.b16 {%0,%1,%2,%3}, [%4];" \
    : "=r"(d0),"=r"(d1),"=r"(d2),"=r"(d3) : "r"(ad))
#define LDSMT(d0,d1,d2,d3,ad) asm volatile( \
    "ldmatrix.sync.aligned.m8n8.x4.trans.shared.b16 {%0,%1,%2,%3}, [%4];" \
    : "=r"(d0),"=r"(d1),"=r"(d2),"=r"(d3) : "r"(ad))
#define CPA16(dst,src) asm volatile( \
    "cp.async.cg.shared.global [%0], [%1], 16;" :: "r"(dst), "l"(src) : "memory")
#define CPCOMMIT() asm volatile("cp.async.commit_group;" ::: "memory")
#define CPWAIT1()  asm volatile("cp.async.wait_group 1;" ::: "memory")
#define CPWAIT0()  asm volatile("cp.async.wait_group 0;" ::: "memory")

// A tile frag addr: 128B rows, swizzle chunk ^= (m&7)
__device__ __forceinline__ uint32_t a_addr(uint32_t aB, int mbase, int ko, int lane) {
    int m  = mbase + (lane & 7) + ((lane >> 3) & 1) * 8;
    int cb = 2 * ko + ((lane >> 4) << 4);
    return aB + m * 128 + (cb ^ ((m & 7) << 4));
}
// B tile frag addr (trans): row k, swizzle chunk ^= (k&7)
__device__ __forceinline__ uint32_t b_addr(uint32_t bB, int nbase, int ko, int lane, int stride) {
    int k  = ko + ((lane >> 3) & 1) * 8 + (lane & 7);
    int nb = nbase + ((lane >> 4) << 3);
    return bB + k * stride + ((2 * nb) ^ ((k & 7) << 4));
}

// ---------------- conversion kernels ----------------
__global__ void cvt_x_kernel(const float* __restrict__ x) {
    size_t i = ((size_t)blockIdx.x * blockDim.x + threadIdx.x) * 4;
    float4 v = *reinterpret_cast<const float4*>(x + i);
    uint2 u; u.x = pk(v.x, v.y); u.y = pk(v.z, v.w);
    *reinterpret_cast<uint2*>(&g_x16[i]) = u;
}
__global__ void cvt_w_kernel(const float* __restrict__ src, size_t dst_off) {
    size_t i = ((size_t)blockIdx.x * blockDim.x + threadIdx.x) * 8;
    float4 v0 = *reinterpret_cast<const float4*>(src + i);
    float4 v1 = *reinterpret_cast<const float4*>(src + i + 4);
    uint4 u;
    u.x = pk(v0.x, v0.y); u.y = pk(v0.z, v0.w);
    u.z = pk(v1.x, v1.y); u.w = pk(v1.z, v1.w);
    *reinterpret_cast<uint4*>(&g_w16[dst_off + i]) = u;
}

__global__ void zero_cnt_kernel() {
    if (threadIdx.x < NEXP) g_cnt[threadIdx.x] = 0;
}

__global__ __launch_bounds__(128) void gate_kernel(const float* __restrict__ x,
                                                   const float* __restrict__ Wg) {
    __shared__ float red[128 * NEXP];
    __shared__ float sc[NEXP];
    int t = blockIdx.x;
    const float* xr = x + (size_t)t * DIM_;
    float acc[NEXP];
#pragma unroll
    for (int e = 0; e < NEXP; e++) acc[e] = 0.f;
    for (int i = threadIdx.x; i < DIM_; i += 128) {
        float xv = xr[i];
        const float4* w4 = reinterpret_cast<const float4*>(Wg + (size_t)i * NEXP);
        float4 wa = w4[0], wb = w4[1];
        acc[0] += xv * wa.x; acc[1] += xv * wa.y;
        acc[2] += xv * wa.z; acc[3] += xv * wa.w;
        acc[4] += xv * wb.x; acc[5] += xv * wb.y;
        acc[6] += xv * wb.z; acc[7] += xv * wb.w;
    }
#pragma unroll
    for (int e = 0; e < NEXP; e++) red[threadIdx.x * NEXP + e] = acc[e];
    __syncthreads();
    if (threadIdx.x < NEXP) {
        int e = threadIdx.x;
        float s = 0.f;
        for (int i = 0; i < 128; i++) s += red[i * NEXP + e];
        sc[e] = s;
    }
    __syncthreads();
    if (threadIdx.x == 0) {
        int i1 = 0;
#pragma unroll
        for (int e = 1; e < NEXP; e++) if (sc[e] > sc[i1]) i1 = e;
        int i2 = (i1 == 0) ? 1 : 0;
#pragma unroll
        for (int e = 0; e < NEXP; e++) if (e != i1 && sc[e] > sc[i2]) i2 = e;
        float e2 = expf(sc[i2] - sc[i1]);
        float wa = 1.f / (1.f + e2);
        float wb = e2 / (1.f + e2);
        int s1 = atomicAdd(&g_cnt[i1], 1);
        g_tok[i1 * NTOK + s1] = t; g_wt[i1 * NTOK + s1] = wa;
        int s2 = atomicAdd(&g_cnt[i2], 1);
        g_tok[i2 * NTOK + s2] = t; g_wt[i2 * NTOK + s2] = wb;
    }
}

// ---------------- FFN1: X16 @ {w1,w3} + SwiGLU -> g_act ----------------
// BM=128, BN=64/matrix, BKH=64, 3-stage cp.async. smem 3x(16K+8K+8K)=96KB.
__global__ __launch_bounds__(256, 2) void ffn1_kernel() {
    extern __shared__ __align__(128) char smem[];
    __shared__ int toks[128];
    uint32_t sA  = (uint32_t)__cvta_generic_to_shared(smem);          // 3 x 16KB
    uint32_t sB1 = sA + 49152;                                        // 3 x 8KB
    uint32_t sB3 = sA + 73728;                                        // 3 x 8KB

    int e = blockIdx.z, cnt = g_cnt[e];
    int m0 = blockIdx.x * 128;
    if (m0 >= cnt) return;
    int n0 = blockIdx.y * 64;
    int base = 0;
#pragma unroll
    for (int i = 0; i < NEXP; i++) base += (i < e) ? g_cnt[i] : 0;
    const __half* W1 = g_w16 + (size_t)e * WSZ;
    const __half* W3 = g_w16 + W3OFF + (size_t)e * WSZ;

    int tid = threadIdx.x, lane = tid & 31, w = tid >> 5;
    if (tid < 128) {
        int m = m0 + tid;
        toks[tid] = (m < cnt) ? g_tok[e * NTOK + m] : 0;
    }
    __syncthreads();

    // loaders
    int ar = tid >> 1, ach0 = (tid & 1) * 4;         // A: row ar, 4 chunks
    const __half* asrc = g_x16 + (size_t)toks[ar] * DIM_;
    uint32_t aswz = (uint32_t)(ar & 7) << 4;
    int kb = tid >> 2, bch0 = (tid & 3) * 2;         // B: row kb, 2 chunks
    uint32_t bswz = (uint32_t)(kb & 7) << 4;

    int wm = (w >> 1) * 32, wn = (w & 1) * 32;
    int r = lane >> 2, q = lane & 3;

    float c1[2][4][4], c3[2][4][4];
#pragma unroll
    for (int i = 0; i < 2; i++)
#pragma unroll
        for (int j = 0; j < 4; j++)
#pragma unroll
            for (int k = 0; k < 4; k++) { c1[i][j][k] = 0.f; c3[i][j][k] = 0.f; }

#define F1_CPA(K0, ST) do {                                                        \
    uint32_t a_ = sA + (ST) * 16384 + ar * 128;                                    \
    _Pragma("unroll")                                                              \
    for (int j = 0; j < 4; j++) {                                                  \
        uint32_t ch = ach0 + j;                                                    \
        CPA16(a_ + ((ch * 16) ^ aswz), asrc + (K0) + ch * 8);                      \
    }                                                                              \
    uint32_t b1_ = sB1 + (ST) * 8192 + kb * 128;                                   \
    uint32_t b3_ = sB3 + (ST) * 8192 + kb * 128;                                   \
    const __half* w1p = W1 + (size_t)((K0) + kb) * HID_ + n0;                      \
    const __half* w3p = W3 + (size_t)((K0) + kb) * HID_ + n0;                      \
    _Pragma("unroll")                                                              \
    for (int j = 0; j < 2; j++) {                                                  \
        uint32_t ch = bch0 + j;                                                    \
        CPA16(b1_ + ((ch * 16) ^ bswz), w1p + ch * 8);                             \
        CPA16(b3_ + ((ch * 16) ^ bswz), w3p + ch * 8);                             \
    }                                                                              \
    CPCOMMIT();                                                                    \
} while (0)

    F1_CPA(0, 0);
    F1_CPA(BKH, 1);

    for (int t = 0; t < NT1; t++) {
        int st = t % 3;
        if (t == NT1 - 1) CPWAIT0(); else CPWAIT1();   // tail: no younger group exists
        __syncthreads();
        if (t + 2 < NT1) F1_CPA((t + 2) * BKH, (t + 2) % 3);
        uint32_t aB = sA + st * 16384, b1B = sB1 + st * 8192, b3B = sB3 + st * 8192;
#pragma unroll
        for (int kk = 0; kk < 4; kk++) {
            int ko = kk << 4;
            unsigned a0[4], a1[4], f1[4][2], f3[4][2];
            LDSM(a0[0], a0[1], a0[2], a0[3], a_addr(aB, wm, ko, lane));
            LDSM(a1[0], a1[1], a1[2], a1[3], a_addr(aB, wm + 16, ko, lane));
            LDSMT(f1[0][0], f1[0][1], f1[1][0], f1[1][1], b_addr(b1B, wn, ko, lane, 128));
            LDSMT(f1[2][0], f1[2][1], f1[3][0], f1[3][1], b_addr(b1B, wn + 16, ko, lane, 128));
            LDSMT(f3[0][0], f3[0][1], f3[1][0], f3[1][1], b_addr(b3B, wn, ko, lane, 128));
            LDSMT(f3[2][0], f3[2][1], f3[3][0], f3[3][1], b_addr(b3B, wn + 16, ko, lane, 128));
#pragma unroll
            for (int ni = 0; ni < 4; ni++) {
                mma16(c1[0][ni], a0, f1[ni]); mma16(c1[1][ni], a1, f1[ni]);
                mma16(c3[0][ni], a0, f3[ni]); mma16(c3[1][ni], a1, f3[ni]);
            }
        }
    }

    // epilogue: SwiGLU -> g_act
#pragma unroll
    for (int mi = 0; mi < 2; mi++) {
#pragma unroll
        for (int rr = 0; rr < 2; rr++) {
            int m = m0 + wm + (mi << 4) + r + (rr << 3);
            if (m < cnt) {
                size_t rowoff = (size_t)(base + m) * HID_;
#pragma unroll
                for (int ni = 0; ni < 4; ni++) {
                    int col = n0 + wn + (ni << 3) + (q << 1);
                    float u0 = c1[mi][ni][(rr << 1)],     v0 = c3[mi][ni][(rr << 1)];
                    float u1 = c1[mi][ni][(rr << 1) + 1], v1 = c3[mi][ni][(rr << 1) + 1];
                    float h0 = (u0 / (1.f + expf(-u0))) * v0;
                    float h1 = (u1 / (1.f + expf(-u1))) * v1;
                    *reinterpret_cast<unsigned*>(&g_act[rowoff + col]) = pk(h0, h1);
                }
            }
        }
    }
}

// ---------------- FFN2: g_act @ w2 -> weighted scatter ----------------
// BM=128, BN=128, BKH=64, 3-stage. smem 3x(16K+16K)=96KB.
__global__ __launch_bounds__(256, 2) void ffn2_kernel(float* __restrict__ out) {
    extern __shared__ __align__(128) char smem[];
    uint32_t sA = (uint32_t)__cvta_generic_to_shared(smem);           // 3 x 16KB
    uint32_t sB = sA + 49152;                                         // 3 x 16KB

    int e = blockIdx.z, cnt = g_cnt[e];
    int m0 = blockIdx.x * 128;
    if (m0 >= cnt) return;
    int n0 = blockIdx.y * 128;
    int base = 0;
#pragma unroll
    for (int i = 0; i < NEXP; i++) base += (i < e) ? g_cnt[i] : 0;
    const __half* W2 = g_w16 + W2OFF + (size_t)e * WSZ;

    int tid = threadIdx.x, lane = tid & 31, w = tid >> 5;
    int ar = tid >> 1, ach0 = (tid & 1) * 4;
    int arow = base + min(m0 + ar, cnt - 1);
    const __half* asrc = g_act + (size_t)arow * HID_;
    uint32_t aswz = (uint32_t)(ar & 7) << 4;
    int kb = tid >> 2, bch0 = (tid & 3) * 4;
    uint32_t bswz = (uint32_t)(kb & 7) << 4;

    int wm = (w >> 1) * 32, wn = (w & 1) * 64;
    int r = lane >> 2, q = lane & 3;

    float c[2][8][4];
#pragma unroll
    for (int i = 0; i < 2; i++)
#pragma unroll
        for (int j = 0; j < 8; j++)
#pragma unroll
            for (int k = 0; k < 4; k++) c[i][j][k] = 0.f;

#define F2_CPA(K0, ST) do {                                                        \
    uint32_t a_ = sA + (ST) * 16384 + ar * 128;                                    \
    _Pragma("unroll")                                                              \
    for (int j = 0; j < 4; j++) {                                                  \
        uint32_t ch = ach0 + j;                                                    \
        CPA16(a_ + ((ch * 16) ^ aswz), asrc + (K0) + ch * 8);                      \
    }                                                                              \
    uint32_t b_ = sB + (ST) * 16384 + kb * 256;                                    \
    const __half* wp = W2 + (size_t)((K0) + kb) * DIM_ + n0;                       \
    _Pragma("unroll")                                                              \
    for (int j = 0; j < 4; j++) {                                                  \
        uint32_t ch = bch0 + j;                                                    \
        CPA16(b_ + ((ch * 16) ^ bswz), wp + ch * 8);                               \
    }                                                                              \
    CPCOMMIT();                                                                    \
} while (0)

    F2_CPA(0, 0);
    F2_CPA(BKH, 1);

    for (int t = 0; t < NT2; t++) {
        int st = t % 3;
        if (t == NT2 - 1) CPWAIT0(); else CPWAIT1();   // tail: no younger group exists
        __syncthreads();
        if (t + 2 < NT2) F2_CPA((t + 2) * BKH, (t + 2) % 3);
        uint32_t aB = sA + st * 16384, bB = sB + st * 16384;
#pragma unroll
        for (int kk = 0; kk < 4; kk++) {
            int ko = kk << 4;
            unsigned a0[4], a1[4], bf[8][2];
            LDSM(a0[0], a0[1], a0[2], a0[3], a_addr(aB, wm, ko, lane));
            LDSM(a1[0], a1[1], a1[2], a1[3], a_addr(aB, wm + 16, ko, lane));
            LDSMT(bf[0][0], bf[0][1], bf[1][0], bf[1][1], b_addr(bB, wn,      ko, lane, 256));
            LDSMT(bf[2][0], bf[2][1], bf[3][0], bf[3][1], b_addr(bB, wn + 16, ko, lane, 256));
            LDSMT(bf[4][0], bf[4][1], bf[5][0], bf[5][1], b_addr(bB, wn + 32, ko, lane, 256));
            LDSMT(bf[6][0], bf[6][1], bf[7][0], bf[7][1], b_addr(bB, wn + 48, ko, lane, 256));
#pragma unroll
            for (int ni = 0; ni < 8; ni++) {
                mma16(c[0][ni], a0, bf[ni]);
                mma16(c[1][ni], a1, bf[ni]);
            }
        }
    }

    // epilogue: weighted scatter-add
#pragma unroll
    for (int mi = 0; mi < 2; mi++) {
#pragma unroll
        for (int rr = 0; rr < 2; rr++) {
            int m = m0 + wm + (mi << 4) + r + (rr << 3);
            if (m < cnt) {
                int tk = g_tok[e * NTOK + m];
                float wgt = g_wt[e * NTOK + m];
                float* orow = out + (size_t)tk * DIM_;
#pragma unroll
                for (int ni = 0; ni < 8; ni++) {
                    int col = n0 + wn + (ni << 3) + (q << 1);
                    atomicAdd(&orow[col],     wgt * c[mi][ni][(rr << 1)]);
                    atomicAdd(&orow[col + 1], wgt * c[mi][ni][(rr << 1) + 1]);
                }
            }
        }
    }
}

// ---------------- launch ----------------
extern "C" void kernel_launch(void* const* d_in, const int* in_sizes, int n_in,
                              void* d_out, int out_size) {
    const float* x  = (const float*)d_in[0];
    const float* Wg = (const float*)d_in[1];
    const float* w1 = (const float*)d_in[2];
    const float* w3 = (const float*)d_in[3];
    const float* w2 = (const float*)d_in[4];
    float* out = (float*)d_out;
    (void)in_sizes; (void)n_in;

    static int attr_done = 0;
    if (!attr_done) {
        cudaFuncSetAttribute(ffn1_kernel, cudaFuncAttributeMaxDynamicSharedMemorySize, 98304);
        cudaFuncSetAttribute(ffn2_kernel, cudaFuncAttributeMaxDynamicSharedMemorySize, 98304);
        attr_done = 1;
    }

    cudaMemsetAsync(out, 0, (size_t)out_size * sizeof(float), 0);
    cvt_x_kernel<<<(NTOK * DIM_) / (256 * 4), 256>>>(x);
    cvt_w_kernel<<<(int)(WSZ * NEXP / (256 * 8)), 256>>>(w1, 0);
    cvt_w_kernel<<<(int)(WSZ * NEXP / (256 * 8)), 256>>>(w3, W3OFF);
    cvt_w_kernel<<<(int)(WSZ * NEXP / (256 * 8)), 256>>>(w2, W2OFF);
    zero_cnt_kernel<<<1, 32>>>();
    gate_kernel<<<NTOK, 128>>>(x, Wg);
    ffn1_kernel<<<dim3(NTOK / 128, HID_ / 64, NEXP), 256, 98304>>>();
    ffn2_kernel<<<dim3(NTOK / 128, DIM_ / 128, NEXP), 256, 98304>>>(out);
}